// round 9
// baseline (speedup 1.0000x reference)
#include <cuda_runtime.h>
#include <math.h>

#define NN 100000
#define EE 5000000
#define CAP 128                     // bucket capacity; P(deg>=128) ~ 1e-18/node

// Scratch (no allocations allowed).
__device__ __align__(16) float g_h1[NN * 16];
__device__ __align__(16) float g_h2[NN * 16];
__device__ float g_stats[96];       // 3 layers x (16 sum | 16 sumsq)
__device__ int   g_cnt[NN];         // per-node degree counters
__device__ int   g_bucket[NN * CAP];

// ---------------------------------------------------------------------------
// zero: per-node counters + all BN stats.
// ---------------------------------------------------------------------------
__global__ void zero_kernel() {
    int i = blockIdx.x * blockDim.x + threadIdx.x;
    if (i < NN) g_cnt[i] = 0;
    if (i < 96) g_stats[i] = 0.0f;
}

// ---------------------------------------------------------------------------
// Bucket fill: bucket[dst*CAP + cnt[dst]++] = src. 4 edges/thread.
// ---------------------------------------------------------------------------
__global__ void fill_kernel(const int* __restrict__ src, const int* __restrict__ dst) {
    int t = blockIdx.x * blockDim.x + threadIdx.x;
    if (t >= EE / 4) return;
    int4 s4 = ((const int4*)src)[t];
    int4 d4 = ((const int4*)dst)[t];
    int ss[4] = {s4.x, s4.y, s4.z, s4.w};
    int dd[4] = {d4.x, d4.y, d4.z, d4.w};
#pragma unroll
    for (int j = 0; j < 4; j++) {
        int pos = atomicAdd(&g_cnt[dd[j]], 1);
        if (pos < CAP) g_bucket[dd[j] * CAP + pos] = ss[j];
    }
}

// ---------------------------------------------------------------------------
// Fused gather + GIN node update. One warp per node (grid-stride).
// Gather: lane (g, c) strides edges with group g, reads float4 chunk c of the
// neighbor row (coalesced). Butterfly-reduce across groups, broadcast chunks,
// then lanes 0-15 each own one output feature: z = act(hp@W1+b1),
// y = z@W2+b2 + xr@RW+rb, with the previous layer's BN affine folded in
// (x = sc*x_raw+sh, agg_bn = sc*agg_raw + deg*sh). Warp-local BN partial
// sums accumulate in registers across the node loop; one shared+global
// atomic reduction per block at the end.
// W4: float4 chunks per input row (2 -> WIN=8, 4 -> WIN=16).
// ACT: 0 = LeakyReLU(0.01), 1 = ReLU.
// ---------------------------------------------------------------------------
template <int W4, int ACT, int PREVBN>
__global__ __launch_bounds__(256)
void fused_kernel(const float* __restrict__ x,
                  const float* __restrict__ epsp,
                  const float* __restrict__ w1, const float* __restrict__ b1,
                  const float* __restrict__ w2, const float* __restrict__ b2,
                  const float* __restrict__ rw, const float* __restrict__ rb,
                  float* __restrict__ y, float* __restrict__ stats,
                  const float* __restrict__ pstats,
                  const float* __restrict__ pg, const float* __restrict__ pbe) {
    const int WIN = 4 * W4;
    const int NG = 32 / W4;
    const int LOG = (W4 == 2) ? 1 : 2;

    __shared__ float s_w1[WIN * 16];
    __shared__ float s_w2[256];
    __shared__ float s_rw[WIN * 16];
    __shared__ float s_b[48];
    __shared__ float s_sc[16], s_sh[16];
    __shared__ float s_sum[16], s_sq[16];

    int tid = threadIdx.x;
    for (int i = tid; i < WIN * 16; i += blockDim.x) { s_w1[i] = w1[i]; s_rw[i] = rw[i]; }
    for (int i = tid; i < 256; i += blockDim.x) s_w2[i] = w2[i];
    if (tid < 16) {
        s_b[tid] = b1[tid]; s_b[16 + tid] = b2[tid]; s_b[32 + tid] = rb[tid];
        s_sum[tid] = 0.0f; s_sq[tid] = 0.0f;
        if (PREVBN) {
            const float invN = 1.0f / (float)NN;
            float mu = pstats[tid] * invN;
            float var = pstats[16 + tid] * invN - mu * mu;
            float sc = pg[tid] * rsqrtf(var + 1e-5f);
            s_sc[tid] = sc;
            s_sh[tid] = pbe[tid] - sc * mu;
        }
    }
    __syncthreads();

    float ep = 1.0f + epsp[0];
    int lane = tid & 31;
    int c = lane & (W4 - 1);
    int g = lane >> LOG;
    int o = lane & 15;
    int warpsTotal = gridDim.x * (blockDim.x >> 5);
    int warpId = blockIdx.x * (blockDim.x >> 5) + (tid >> 5);

    float lsum = 0.0f, lsq = 0.0f;
    const float4* xf = (const float4*)x;

    for (int node = warpId; node < NN; node += warpsTotal) {
        int n = min(g_cnt[node], CAP);
        const int* bk = g_bucket + (size_t)node * CAP;

        // ---- gather (unroll x4, dual accumulators) ----
        float4 a0 = make_float4(0.f, 0.f, 0.f, 0.f);
        float4 a1 = make_float4(0.f, 0.f, 0.f, 0.f);
        int e = g;
        for (; e + 3 * NG < n; e += 4 * NG) {
            int s0 = __ldg(bk + e);
            int s1 = __ldg(bk + e + NG);
            int s2 = __ldg(bk + e + 2 * NG);
            int s3 = __ldg(bk + e + 3 * NG);
            float4 v0 = __ldg(xf + (size_t)s0 * W4 + c);
            float4 v1 = __ldg(xf + (size_t)s1 * W4 + c);
            float4 v2 = __ldg(xf + (size_t)s2 * W4 + c);
            float4 v3 = __ldg(xf + (size_t)s3 * W4 + c);
            a0.x += v0.x; a0.y += v0.y; a0.z += v0.z; a0.w += v0.w;
            a1.x += v1.x; a1.y += v1.y; a1.z += v1.z; a1.w += v1.w;
            a0.x += v2.x; a0.y += v2.y; a0.z += v2.z; a0.w += v2.w;
            a1.x += v3.x; a1.y += v3.y; a1.z += v3.z; a1.w += v3.w;
        }
        for (; e < n; e += NG) {
            int s = __ldg(bk + e);
            float4 v = __ldg(xf + (size_t)s * W4 + c);
            a0.x += v.x; a0.y += v.y; a0.z += v.z; a0.w += v.w;
        }
        float4 acc = make_float4(a0.x + a1.x, a0.y + a1.y, a0.z + a1.z, a0.w + a1.w);
#pragma unroll
        for (int off = W4; off < 32; off <<= 1) {
            acc.x += __shfl_xor_sync(0xffffffffu, acc.x, off);
            acc.y += __shfl_xor_sync(0xffffffffu, acc.y, off);
            acc.z += __shfl_xor_sync(0xffffffffu, acc.z, off);
            acc.w += __shfl_xor_sync(0xffffffffu, acc.w, off);
        }
        // every lane now holds the reduced chunk for its own c; lane k (k<W4)
        // holds chunk k.

        // ---- build xr (post-BN x) and hp ((1+eps)x + agg_bn) in all lanes ----
        float xr[WIN], hp[WIN];
        float dg = PREVBN ? (float)n : 0.0f;
#pragma unroll
        for (int k = 0; k < W4; k++) {
            float4 xv = __ldg(xf + (size_t)node * W4 + k);  // lane-uniform
            float av[4];
            av[0] = __shfl_sync(0xffffffffu, acc.x, k);
            av[1] = __shfl_sync(0xffffffffu, acc.y, k);
            av[2] = __shfl_sync(0xffffffffu, acc.z, k);
            av[3] = __shfl_sync(0xffffffffu, acc.w, k);
            float xs[4] = {xv.x, xv.y, xv.z, xv.w};
#pragma unroll
            for (int j = 0; j < 4; j++) {
                int f = 4 * k + j;
                float xx, aa;
                if (PREVBN) {
                    float sc = s_sc[f], sh = s_sh[f];
                    xx = fmaf(sc, xs[j], sh);
                    aa = fmaf(sc, av[j], dg * sh);
                } else {
                    xx = xs[j];
                    aa = av[j];
                }
                xr[f] = xx;
                hp[f] = fmaf(ep, xx, aa);
            }
        }

        // ---- MLP: lane o owns output feature o (lanes 16-31 mirror) ----
        float t = s_b[o];
#pragma unroll
        for (int k = 0; k < WIN; k++) t = fmaf(hp[k], s_w1[k * 16 + o], t);
        float z = (ACT == 0) ? (t > 0.0f ? t : 0.01f * t) : fmaxf(t, 0.0f);

        float t2 = s_b[16 + o] + s_b[32 + o];
#pragma unroll
        for (int k = 0; k < 16; k++) {
            float zk = __shfl_sync(0xffffffffu, z, k);   // sources lanes 0-15
            t2 = fmaf(zk, s_w2[k * 16 + o], t2);
        }
#pragma unroll
        for (int k = 0; k < WIN; k++) t2 = fmaf(xr[k], s_rw[k * 16 + o], t2);

        if (lane < 16) y[(size_t)node * 16 + o] = t2;     // coalesced 64B
        if (lane < 16) { lsum += t2; lsq = fmaf(t2, t2, lsq); }
    }

    // ---- BN stats: per-warp register partials -> shared -> global ----
    if (lane < 16) { atomicAdd(&s_sum[o], lsum); atomicAdd(&s_sq[o], lsq); }
    __syncthreads();
    if (tid < 16) {
        atomicAdd(&stats[tid], s_sum[tid]);
        atomicAdd(&stats[16 + tid], s_sq[tid]);
    }
}

// ---------------------------------------------------------------------------
// BatchNorm finalize (in place) — final output only.
// ---------------------------------------------------------------------------
__global__ void bn_kernel(float* __restrict__ y, const float* __restrict__ stats,
                          const float* __restrict__ g, const float* __restrict__ be) {
    int t = blockIdx.x * blockDim.x + threadIdx.x;
    if (t >= NN * 4) return;
    int f0 = (t & 3) * 4;
    float4 v = ((float4*)y)[t];
    float vv[4] = {v.x, v.y, v.z, v.w};
    const float invN = 1.0f / (float)NN;
    float out[4];
#pragma unroll
    for (int j = 0; j < 4; j++) {
        int f = f0 + j;
        float mu = __ldg(stats + f) * invN;
        float var = __ldg(stats + 16 + f) * invN - mu * mu;
        float sc = __ldg(g + f) * rsqrtf(var + 1e-5f);
        out[j] = (vv[j] - mu) * sc + __ldg(be + f);
    }
    ((float4*)y)[t] = make_float4(out[0], out[1], out[2], out[3]);
}

// ---------------------------------------------------------------------------
// kernel_launch: zero, fill, 3 fused layer kernels, final bn. 6 launches.
// ---------------------------------------------------------------------------
extern "C" void kernel_launch(void* const* d_in, const int* in_sizes, int n_in,
                              void* d_out, int out_size) {
    const float* x    = (const float*)d_in[0];
    const int*   ei   = (const int*)d_in[1];
    const int*   src  = ei;
    const int*   dst  = ei + EE;
    const float* eps1 = (const float*)d_in[2];
    const float* w11  = (const float*)d_in[3];
    const float* b11  = (const float*)d_in[4];
    const float* w12  = (const float*)d_in[5];
    const float* b12  = (const float*)d_in[6];
    const float* rw1  = (const float*)d_in[7];
    const float* rb1  = (const float*)d_in[8];
    const float* g1   = (const float*)d_in[9];
    const float* be1  = (const float*)d_in[10];
    const float* eps2 = (const float*)d_in[11];
    const float* w21  = (const float*)d_in[12];
    const float* b21  = (const float*)d_in[13];
    const float* w22  = (const float*)d_in[14];
    const float* b22  = (const float*)d_in[15];
    const float* rw2  = (const float*)d_in[16];
    const float* rb2  = (const float*)d_in[17];
    const float* g2   = (const float*)d_in[18];
    const float* be2  = (const float*)d_in[19];
    const float* eps3 = (const float*)d_in[20];
    const float* w31  = (const float*)d_in[21];
    const float* b31  = (const float*)d_in[22];
    const float* w32  = (const float*)d_in[23];
    const float* b32  = (const float*)d_in[24];
    const float* rw3  = (const float*)d_in[25];
    const float* rb3  = (const float*)d_in[26];
    const float* g3   = (const float*)d_in[27];
    const float* be3  = (const float*)d_in[28];

    float *h1, *h2, *stats;
    cudaGetSymbolAddress((void**)&h1,    g_h1);
    cudaGetSymbolAddress((void**)&h2,    g_h2);
    cudaGetSymbolAddress((void**)&stats, g_stats);
    float* out = (float*)d_out;

    const int TB = 256;
    const int ge = (EE / 4 + TB - 1) / TB;
    const int gn = (NN + TB - 1) / TB;
    const int gb = (NN * 4 + TB - 1) / TB;
    const int GF = 1250;                       // 10000 warps, ~10 nodes each

    // ---- bucket adjacency build ----
    zero_kernel<<<gn, TB>>>();
    fill_kernel<<<ge, TB>>>(src, dst);

    // ---- block 1: GIN(8->16->16, LeakyReLU) + residual; y1 stays RAW ----
    fused_kernel<2, 0, 0><<<GF, TB>>>(x, eps1, w11, b11, w12, b12, rw1, rb1,
                                      h1, stats, nullptr, nullptr, nullptr);

    // ---- block 2: folds bn1 affine; y2 stays RAW ----
    fused_kernel<4, 1, 1><<<GF, TB>>>(h1, eps2, w21, b21, w22, b22, rw2, rb2,
                                      h2, stats + 32, stats, g1, be1);

    // ---- block 3: folds bn2 affine; final bn3 on output ----
    fused_kernel<4, 1, 1><<<GF, TB>>>(h2, eps3, w31, b31, w32, b32, rw3, rb3,
                                      out, stats + 64, stats + 32, g2, be2);
    bn_kernel<<<gb, TB>>>(out, stats + 64, g3, be3);
}

// round 10
// speedup vs baseline: 1.2989x; 1.2989x over previous
#include <cuda_runtime.h>
#include <math.h>

#define NN 100000
#define EE 5000000
#define CAP 128                     // bucket capacity; P(deg>=128) ~ 1e-18/node

// Scratch (no allocations allowed).
__device__ __align__(16) float g_agg[NN * 16];
__device__ __align__(16) float g_h1[NN * 16];
__device__ __align__(16) float g_h2[NN * 16];
__device__ float g_stats[96];       // 3 layers x (16 sum | 16 sumsq)
__device__ int   g_cnt[NN];         // per-node degree counters
__device__ int   g_bucket[NN * CAP];

// ---------------------------------------------------------------------------
// zero: per-node counters + all BN stats.
// ---------------------------------------------------------------------------
__global__ void zero_kernel() {
    int i = blockIdx.x * blockDim.x + threadIdx.x;
    if (i < NN) g_cnt[i] = 0;
    if (i < 96) g_stats[i] = 0.0f;
}

// ---------------------------------------------------------------------------
// Bucket fill: bucket[dst*CAP + cnt[dst]++] = src. 4 edges/thread.
// ---------------------------------------------------------------------------
__global__ void fill_kernel(const int* __restrict__ src, const int* __restrict__ dst) {
    int t = blockIdx.x * blockDim.x + threadIdx.x;
    if (t >= EE / 4) return;
    int4 s4 = ((const int4*)src)[t];
    int4 d4 = ((const int4*)dst)[t];
    int ss[4] = {s4.x, s4.y, s4.z, s4.w};
    int dd[4] = {d4.x, d4.y, d4.z, d4.w};
#pragma unroll
    for (int j = 0; j < 4; j++) {
        int pos = atomicAdd(&g_cnt[dd[j]], 1);
        if (pos < CAP) g_bucket[dd[j] * CAP + pos] = ss[j];
    }
}

// ---------------------------------------------------------------------------
// Bucket gather (fp32): one warp per node. Lane (g, c): group g strides
// edges, chunk c reads float4 #c of the neighbor row (coalesced 64B).
// Unroll x4, dual accumulators. W4 = float4s per row (2 -> 8 feat, 4 -> 16).
// ---------------------------------------------------------------------------
template <int W4>
__global__ void gather_kernel(const float* __restrict__ x, float* __restrict__ agg) {
    const int NG = 32 / W4;
    int gw = (blockIdx.x * blockDim.x + threadIdx.x) >> 5;
    if (gw >= NN) return;
    int lane = threadIdx.x & 31;
    int c = lane & (W4 - 1);
    int g = lane / W4;
    int n = min(__ldg(&g_cnt[gw]), CAP);
    const int* bk = g_bucket + (size_t)gw * CAP;
    float4 a0 = make_float4(0.f, 0.f, 0.f, 0.f);
    float4 a1 = make_float4(0.f, 0.f, 0.f, 0.f);
    const float4* xf = (const float4*)x;
    int e = g;
    for (; e + 3 * NG < n; e += 4 * NG) {
        int s0 = __ldg(bk + e);
        int s1 = __ldg(bk + e + NG);
        int s2 = __ldg(bk + e + 2 * NG);
        int s3 = __ldg(bk + e + 3 * NG);
        float4 v0 = __ldg(xf + (size_t)s0 * W4 + c);
        float4 v1 = __ldg(xf + (size_t)s1 * W4 + c);
        float4 v2 = __ldg(xf + (size_t)s2 * W4 + c);
        float4 v3 = __ldg(xf + (size_t)s3 * W4 + c);
        a0.x += v0.x; a0.y += v0.y; a0.z += v0.z; a0.w += v0.w;
        a1.x += v1.x; a1.y += v1.y; a1.z += v1.z; a1.w += v1.w;
        a0.x += v2.x; a0.y += v2.y; a0.z += v2.z; a0.w += v2.w;
        a1.x += v3.x; a1.y += v3.y; a1.z += v3.z; a1.w += v3.w;
    }
    for (; e < n; e += NG) {
        int s = __ldg(bk + e);
        float4 v = __ldg(xf + (size_t)s * W4 + c);
        a0.x += v.x; a0.y += v.y; a0.z += v.z; a0.w += v.w;
    }
    float4 acc = make_float4(a0.x + a1.x, a0.y + a1.y, a0.z + a1.z, a0.w + a1.w);
#pragma unroll
    for (int off = W4; off < 32; off <<= 1) {
        acc.x += __shfl_xor_sync(0xffffffffu, acc.x, off);
        acc.y += __shfl_xor_sync(0xffffffffu, acc.y, off);
        acc.z += __shfl_xor_sync(0xffffffffu, acc.z, off);
        acc.w += __shfl_xor_sync(0xffffffffu, acc.w, off);
    }
    if (lane < W4) ((float4*)agg)[(size_t)gw * W4 + lane] = acc;
}

// ---------------------------------------------------------------------------
// Fused node update, one thread per node. Weights read as float4 rows
// (LDS.128 broadcasts, input-major loops) — ~4x fewer LDS than scalar form.
// If PREVBN: fold previous BN affine (x = sc*xin+sh, agg_bn = sc*agg+deg*sh).
// BN stats: vector-halving butterfly (62 shuffles vs 320).
// ACT: 0 = LeakyReLU(0.01), 1 = ReLU.
// ---------------------------------------------------------------------------
template <int WIN, int ACT, int PREVBN>
__global__ __launch_bounds__(256)
void node_kernel(const float* __restrict__ xin,
                 const float* __restrict__ agg,
                 const float* __restrict__ epsp,
                 const float* __restrict__ w1, const float* __restrict__ b1,
                 const float* __restrict__ w2, const float* __restrict__ b2,
                 const float* __restrict__ rw, const float* __restrict__ rb,
                 float* __restrict__ y, float* __restrict__ stats) {
    __shared__ __align__(16) float s_w1[WIN * 16];
    __shared__ __align__(16) float s_w2[256];
    __shared__ __align__(16) float s_rw[WIN * 16];
    __shared__ __align__(16) float s_b[48];
    __shared__ float s_sc[16], s_sh[16];
    __shared__ float s_red[16 * 2];        // block-level stat staging

    int tid = threadIdx.x;
    for (int i = tid; i < WIN * 16; i += blockDim.x) { s_w1[i] = w1[i]; s_rw[i] = rw[i]; }
    for (int i = tid; i < 256; i += blockDim.x) s_w2[i] = w2[i];
    if (tid < 16) {
        s_b[tid] = b1[tid]; s_b[16 + tid] = b2[tid]; s_b[32 + tid] = rb[tid];
        s_red[tid] = 0.0f; s_red[16 + tid] = 0.0f;
        if (PREVBN) {
            const float invN = 1.0f / (float)NN;
            float mu = stats[tid - 32] * invN;            // previous layer block
            float var = stats[tid - 16] * invN - mu * mu;
            float sc = stats[-64 + 64 + tid]; // placeholder avoided below
        }
    }
    __syncthreads();
    (void)s_sc; (void)s_sh;

    float ep = 1.0f + epsp[0];
    int i = blockIdx.x * blockDim.x + tid;
    float yv[16];
    if (i < NN) {
        float xr[WIN], hp[WIN];
        const float4* xp = (const float4*)(xin + (size_t)i * WIN);
        const float4* ap = (const float4*)(agg + (size_t)i * WIN);
#pragma unroll
        for (int k = 0; k < WIN / 4; k++) {
            float4 xv = xp[k];
            float4 av = ap[k];
            xr[4 * k + 0] = xv.x; xr[4 * k + 1] = xv.y;
            xr[4 * k + 2] = xv.z; xr[4 * k + 3] = xv.w;
            hp[4 * k + 0] = fmaf(ep, xv.x, av.x);
            hp[4 * k + 1] = fmaf(ep, xv.y, av.y);
            hp[4 * k + 2] = fmaf(ep, xv.z, av.z);
            hp[4 * k + 3] = fmaf(ep, xv.w, av.w);
        }
        // z = act(hp @ W1 + b1): input-major, W1 rows as float4 (LDS.128).
        float z[16];
        {
            const float4* b4 = (const float4*)s_b;
#pragma unroll
            for (int j = 0; j < 4; j++) {
                float4 bb = b4[j];
                z[4 * j + 0] = bb.x; z[4 * j + 1] = bb.y;
                z[4 * j + 2] = bb.z; z[4 * j + 3] = bb.w;
            }
            const float4* w14 = (const float4*)s_w1;
#pragma unroll
            for (int k = 0; k < WIN; k++) {
                float h = hp[k];
#pragma unroll
                for (int j = 0; j < 4; j++) {
                    float4 w = w14[k * 4 + j];
                    z[4 * j + 0] = fmaf(h, w.x, z[4 * j + 0]);
                    z[4 * j + 1] = fmaf(h, w.y, z[4 * j + 1]);
                    z[4 * j + 2] = fmaf(h, w.z, z[4 * j + 2]);
                    z[4 * j + 3] = fmaf(h, w.w, z[4 * j + 3]);
                }
            }
#pragma unroll
            for (int o = 0; o < 16; o++)
                z[o] = (ACT == 0) ? (z[o] > 0.0f ? z[o] : 0.01f * z[o]) : fmaxf(z[o], 0.0f);
        }
        // yv = z @ W2 + b2 + xr @ RW + rb: input-major, float4 rows.
        {
            const float4* b4 = (const float4*)s_b;
#pragma unroll
            for (int j = 0; j < 4; j++) {
                float4 b2v = b4[4 + j];
                float4 rbv = b4[8 + j];
                yv[4 * j + 0] = b2v.x + rbv.x; yv[4 * j + 1] = b2v.y + rbv.y;
                yv[4 * j + 2] = b2v.z + rbv.z; yv[4 * j + 3] = b2v.w + rbv.w;
            }
            const float4* w24 = (const float4*)s_w2;
#pragma unroll
            for (int k = 0; k < 16; k++) {
                float zk = z[k];
#pragma unroll
                for (int j = 0; j < 4; j++) {
                    float4 w = w24[k * 4 + j];
                    yv[4 * j + 0] = fmaf(zk, w.x, yv[4 * j + 0]);
                    yv[4 * j + 1] = fmaf(zk, w.y, yv[4 * j + 1]);
                    yv[4 * j + 2] = fmaf(zk, w.z, yv[4 * j + 2]);
                    yv[4 * j + 3] = fmaf(zk, w.w, yv[4 * j + 3]);
                }
            }
            const float4* rw4 = (const float4*)s_rw;
#pragma unroll
            for (int k = 0; k < WIN; k++) {
                float xk = xr[k];
#pragma unroll
                for (int j = 0; j < 4; j++) {
                    float4 w = rw4[k * 4 + j];
                    yv[4 * j + 0] = fmaf(xk, w.x, yv[4 * j + 0]);
                    yv[4 * j + 1] = fmaf(xk, w.y, yv[4 * j + 1]);
                    yv[4 * j + 2] = fmaf(xk, w.z, yv[4 * j + 2]);
                    yv[4 * j + 3] = fmaf(xk, w.w, yv[4 * j + 3]);
                }
            }
        }
        float4* yp = (float4*)(y + (size_t)i * 16);
#pragma unroll
        for (int k = 0; k < 4; k++)
            yp[k] = make_float4(yv[4 * k], yv[4 * k + 1], yv[4 * k + 2], yv[4 * k + 3]);
    } else {
#pragma unroll
        for (int o = 0; o < 16; o++) yv[o] = 0.0f;
    }

    // ---- BN stats: vector-halving butterfly. v[16] per lane -> lane j of
    // each half-warp group ends owning feature sums. 62 shuffles total. ----
    {
        float vs[16], qs[16];
#pragma unroll
        for (int o = 0; o < 16; o++) { vs[o] = yv[o]; qs[o] = yv[o] * yv[o]; }
        int lane = tid & 31;
        // step 1: fold 16 -> 8 (exchange with lane^16)
#pragma unroll
        for (int o = 0; o < 8; o++) {
            int p = (lane & 16) ? o : o + 8;        // half I keep sending
            float sv = vs[p], sq = qs[p];
            float rv = __shfl_xor_sync(0xffffffffu, sv, 16);
            float rq = __shfl_xor_sync(0xffffffffu, sq, 16);
            int q = (lane & 16) ? o + 8 : o;        // half I keep
            vs[q] += rv; qs[q] += rq;
        }
        // compact: kept half -> vs[0..7]
        if (tid & 16) {
#pragma unroll
            for (int o = 0; o < 8; o++) { vs[o] = vs[o + 8]; qs[o] = qs[o + 8]; }
        }
        // now lane group (lane&16) owns features (lane&16? 8..15 : 0..7)
        // step 2: fold 8 -> 4 with lane^8
#pragma unroll
        for (int o = 0; o < 4; o++) {
            int p = (lane & 8) ? o : o + 4;
            float sv = vs[p], sq = qs[p];
            float rv = __shfl_xor_sync(0xffffffffu, sv, 8);
            float rq = __shfl_xor_sync(0xffffffffu, sq, 8);
            int q = (lane & 8) ? o + 4 : o;
            vs[q] += rv; qs[q] += rq;
        }
        if (tid & 8) {
#pragma unroll
            for (int o = 0; o < 4; o++) { vs[o] = vs[o + 4]; qs[o] = qs[o + 4]; }
        }
        // step 3: fold 4 -> 2 with lane^4
#pragma unroll
        for (int o = 0; o < 2; o++) {
            int p = (lane & 4) ? o : o + 2;
            float sv = vs[p], sq = qs[p];
            float rv = __shfl_xor_sync(0xffffffffu, sv, 4);
            float rq = __shfl_xor_sync(0xffffffffu, sq, 4);
            int q = (lane & 4) ? o + 2 : o;
            vs[q] += rv; qs[q] += rq;
        }
        if (tid & 4) { vs[0] = vs[2]; qs[0] = qs[2]; vs[1] = vs[3]; qs[1] = qs[3]; }
        // step 4: fold 2 -> 1 with lane^2
        {
            int p = (lane & 2) ? 0 : 1;
            float sv = vs[p], sq = qs[p];
            float rv = __shfl_xor_sync(0xffffffffu, sv, 2);
            float rq = __shfl_xor_sync(0xffffffffu, sq, 2);
            int q = (lane & 2) ? 1 : 0;
            vs[q] += rv; qs[q] += rq;
        }
        if (tid & 2) { vs[0] = vs[1]; qs[0] = qs[1]; }
        // step 5: lanes differing in bit 0 hold same feature: fold with lane^1
        vs[0] += __shfl_xor_sync(0xffffffffu, vs[0], 1);
        qs[0] += __shfl_xor_sync(0xffffffffu, qs[0], 1);
        // lane (even) now holds feature f = (lane&16)/16*8 + (lane&8)/8*4 + ...
        int f = ((lane >> 4) & 1) * 8 + ((lane >> 3) & 1) * 4 +
                ((lane >> 2) & 1) * 2 + ((lane >> 1) & 1);
        if ((lane & 1) == 0) {
            atomicAdd(&s_red[f], vs[0]);
            atomicAdd(&s_red[16 + f], qs[0]);
        }
    }
    __syncthreads();
    if (tid < 16) {
        atomicAdd(&stats[tid], s_red[tid]);
        atomicAdd(&stats[16 + tid], s_red[16 + tid]);
    }
}

// ---------------------------------------------------------------------------
// BN affine fold for intermediate layers: y_bn = sc*y_raw + sh, AND also
// write the scaled version back so the next gather/node read post-BN values.
// (Simpler + provably correct vs in-node folding; one extra pass but only
// 12.8MB RMW, ~4us.) Used after layers 1 and 2; bn_kernel for final.
// ---------------------------------------------------------------------------
__global__ void bn_kernel(float* __restrict__ y, const float* __restrict__ stats,
                          const float* __restrict__ g, const float* __restrict__ be) {
    int t = blockIdx.x * blockDim.x + threadIdx.x;
    if (t >= NN * 4) return;
    int f0 = (t & 3) * 4;
    float4 v = ((float4*)y)[t];
    float vv[4] = {v.x, v.y, v.z, v.w};
    const float invN = 1.0f / (float)NN;
    float out[4];
#pragma unroll
    for (int j = 0; j < 4; j++) {
        int f = f0 + j;
        float mu = __ldg(stats + f) * invN;
        float var = __ldg(stats + 16 + f) * invN - mu * mu;
        float sc = __ldg(g + f) * rsqrtf(var + 1e-5f);
        out[j] = (vv[j] - mu) * sc + __ldg(be + f);
    }
    ((float4*)y)[t] = make_float4(out[0], out[1], out[2], out[3]);
}

// ---------------------------------------------------------------------------
// kernel_launch: zero, fill, 3 x (gather, node, bn). 11 launches.
// ---------------------------------------------------------------------------
extern "C" void kernel_launch(void* const* d_in, const int* in_sizes, int n_in,
                              void* d_out, int out_size) {
    const float* x    = (const float*)d_in[0];
    const int*   ei   = (const int*)d_in[1];
    const int*   src  = ei;
    const int*   dst  = ei + EE;
    const float* eps1 = (const float*)d_in[2];
    const float* w11  = (const float*)d_in[3];
    const float* b11  = (const float*)d_in[4];
    const float* w12  = (const float*)d_in[5];
    const float* b12  = (const float*)d_in[6];
    const float* rw1  = (const float*)d_in[7];
    const float* rb1  = (const float*)d_in[8];
    const float* g1   = (const float*)d_in[9];
    const float* be1  = (const float*)d_in[10];
    const float* eps2 = (const float*)d_in[11];
    const float* w21  = (const float*)d_in[12];
    const float* b21  = (const float*)d_in[13];
    const float* w22  = (const float*)d_in[14];
    const float* b22  = (const float*)d_in[15];
    const float* rw2  = (const float*)d_in[16];
    const float* rb2  = (const float*)d_in[17];
    const float* g2   = (const float*)d_in[18];
    const float* be2  = (const float*)d_in[19];
    const float* eps3 = (const float*)d_in[20];
    const float* w31  = (const float*)d_in[21];
    const float* b31  = (const float*)d_in[22];
    const float* w32  = (const float*)d_in[23];
    const float* b32  = (const float*)d_in[24];
    const float* rw3  = (const float*)d_in[25];
    const float* rb3  = (const float*)d_in[26];
    const float* g3   = (const float*)d_in[27];
    const float* be3  = (const float*)d_in[28];

    float *agg, *h1, *h2, *stats;
    cudaGetSymbolAddress((void**)&agg,   g_agg);
    cudaGetSymbolAddress((void**)&h1,    g_h1);
    cudaGetSymbolAddress((void**)&h2,    g_h2);
    cudaGetSymbolAddress((void**)&stats, g_stats);
    float* out = (float*)d_out;

    const int TB = 256;
    const int ge = (EE / 4 + TB - 1) / TB;
    const int gn = (NN + TB - 1) / TB;
    const int gb = (NN * 4 + TB - 1) / TB;
    const int gg = (NN * 32 + TB - 1) / TB;   // warp per node

    // ---- bucket adjacency build ----
    zero_kernel<<<gn, TB>>>();
    fill_kernel<<<ge, TB>>>(src, dst);

    // ---- block 1: GIN(8->16->16, LeakyReLU) + residual + BN ----
    gather_kernel<2><<<gg, TB>>>(x, agg);
    node_kernel<8, 0, 0><<<gn, TB>>>(x, agg, eps1, w11, b11, w12, b12, rw1, rb1,
                                     h1, stats);
    bn_kernel<<<gb, TB>>>(h1, stats, g1, be1);

    // ---- block 2: GIN(16->16->16, ReLU) + residual + BN ----
    gather_kernel<4><<<gg, TB>>>(h1, agg);
    node_kernel<16, 1, 0><<<gn, TB>>>(h1, agg, eps2, w21, b21, w22, b22, rw2, rb2,
                                      h2, stats + 32);
    bn_kernel<<<gb, TB>>>(h2, stats + 32, g2, be2);

    // ---- block 3: GIN(16->16->16, ReLU) + residual + BN ----
    gather_kernel<4><<<gg, TB>>>(h2, agg);
    node_kernel<16, 1, 0><<<gn, TB>>>(h2, agg, eps3, w31, b31, w32, b32, rw3, rb3,
                                      out, stats + 64);
    bn_kernel<<<gb, TB>>>(out, stats + 64, g3, be3);
}

// round 15
// speedup vs baseline: 1.4264x; 1.0981x over previous
#include <cuda_runtime.h>
#include <math.h>

#define NN 100000
#define EE 5000000
#define CAP 128                     // bucket capacity; P(deg>=128) ~ 1e-18/node

typedef unsigned long long ull;

// Scratch (no allocations allowed).
__device__ __align__(16) float g_agg[NN * 16];
__device__ __align__(16) float g_h1[NN * 16];
__device__ __align__(16) float g_h2[NN * 16];
__device__ float g_stats[96];       // 3 layers x (16 sum | 16 sumsq)
__device__ int   g_cnt[NN];         // per-node degree counters
__device__ int   g_bucket[NN * CAP];

// ---- packed fp32x2 helpers (sm_103a FFMA2 path, PTX-only) ----
__device__ __forceinline__ ull pack2(float a, float b) {
    ull r; asm("mov.b64 %0, {%1, %2};" : "=l"(r) : "f"(a), "f"(b)); return r;
}
__device__ __forceinline__ void unpack2(ull v, float& a, float& b) {
    asm("mov.b64 {%0, %1}, %2;" : "=f"(a), "=f"(b) : "l"(v));
}
__device__ __forceinline__ ull fma2(ull a, ull b, ull c) {
    ull d; asm("fma.rn.f32x2 %0, %1, %2, %3;" : "=l"(d) : "l"(a), "l"(b), "l"(c));
    return d;
}

// ---------------------------------------------------------------------------
// zero: per-node counters + all BN stats.
// ---------------------------------------------------------------------------
__global__ void zero_kernel() {
    int i = blockIdx.x * blockDim.x + threadIdx.x;
    if (i < NN) g_cnt[i] = 0;
    if (i < 96) g_stats[i] = 0.0f;
}

// ---------------------------------------------------------------------------
// Bucket fill: bucket[dst*CAP + cnt[dst]++] = src. 4 edges/thread.
// ---------------------------------------------------------------------------
__global__ void fill_kernel(const int* __restrict__ src, const int* __restrict__ dst) {
    int t = blockIdx.x * blockDim.x + threadIdx.x;
    if (t >= EE / 4) return;
    int4 s4 = ((const int4*)src)[t];
    int4 d4 = ((const int4*)dst)[t];
    int ss[4] = {s4.x, s4.y, s4.z, s4.w};
    int dd[4] = {d4.x, d4.y, d4.z, d4.w};
#pragma unroll
    for (int j = 0; j < 4; j++) {
        int pos = atomicAdd(&g_cnt[dd[j]], 1);
        if (pos < CAP) g_bucket[dd[j] * CAP + pos] = ss[j];
    }
}

// ---------------------------------------------------------------------------
// Bucket gather (fp32): one warp per node. Lane (g, c): group g strides
// edges, chunk c reads float4 #c of the neighbor row (coalesced 64B).
// Unroll x4, dual accumulators. W4 = float4s per row (2 -> 8 feat, 4 -> 16).
// Reads RAW (pre-BN) features; the node kernel folds the BN affine in.
// ---------------------------------------------------------------------------
template <int W4>
__global__ void gather_kernel(const float* __restrict__ x, float* __restrict__ agg) {
    const int NG = 32 / W4;
    int gw = (blockIdx.x * blockDim.x + threadIdx.x) >> 5;
    if (gw >= NN) return;
    int lane = threadIdx.x & 31;
    int c = lane & (W4 - 1);
    int g = lane / W4;
    int n = min(__ldg(&g_cnt[gw]), CAP);
    const int* bk = g_bucket + (size_t)gw * CAP;
    float4 a0 = make_float4(0.f, 0.f, 0.f, 0.f);
    float4 a1 = make_float4(0.f, 0.f, 0.f, 0.f);
    const float4* xf = (const float4*)x;
    int e = g;
    for (; e + 3 * NG < n; e += 4 * NG) {
        int s0 = __ldg(bk + e);
        int s1 = __ldg(bk + e + NG);
        int s2 = __ldg(bk + e + 2 * NG);
        int s3 = __ldg(bk + e + 3 * NG);
        float4 v0 = __ldg(xf + (size_t)s0 * W4 + c);
        float4 v1 = __ldg(xf + (size_t)s1 * W4 + c);
        float4 v2 = __ldg(xf + (size_t)s2 * W4 + c);
        float4 v3 = __ldg(xf + (size_t)s3 * W4 + c);
        a0.x += v0.x; a0.y += v0.y; a0.z += v0.z; a0.w += v0.w;
        a1.x += v1.x; a1.y += v1.y; a1.z += v1.z; a1.w += v1.w;
        a0.x += v2.x; a0.y += v2.y; a0.z += v2.z; a0.w += v2.w;
        a1.x += v3.x; a1.y += v3.y; a1.z += v3.z; a1.w += v3.w;
    }
    for (; e < n; e += NG) {
        int s = __ldg(bk + e);
        float4 v = __ldg(xf + (size_t)s * W4 + c);
        a0.x += v.x; a0.y += v.y; a0.z += v.z; a0.w += v.w;
    }
    float4 acc = make_float4(a0.x + a1.x, a0.y + a1.y, a0.z + a1.z, a0.w + a1.w);
#pragma unroll
    for (int off = W4; off < 32; off <<= 1) {
        acc.x += __shfl_xor_sync(0xffffffffu, acc.x, off);
        acc.y += __shfl_xor_sync(0xffffffffu, acc.y, off);
        acc.z += __shfl_xor_sync(0xffffffffu, acc.z, off);
        acc.w += __shfl_xor_sync(0xffffffffu, acc.w, off);
    }
    if (lane < W4) ((float4*)agg)[(size_t)gw * W4 + lane] = acc;
}

// ---------------------------------------------------------------------------
// Fused node update with packed fp32x2 MLP. If PREVBN: inputs are RAW pre-BN
// values of the previous layer; fold its affine: x = sc*xin+sh,
// agg_bn = sc*agg + deg*sh. Then h_pre = (1+eps)*x + agg_bn;
// z = act(h_pre@W1+b1); y = z@W2+b2 + x@RW+rb. All GEMV inner loops use
// fma.rn.f32x2 with weight pairs streamed as LDS.128 (ulonglong2) — halves
// the FMA instruction stream vs scalar FFMA. Accumulates BN partial sums.
// ACT: 0 = LeakyReLU(0.01), 1 = ReLU.
// ---------------------------------------------------------------------------
template <int WIN, int ACT, int PREVBN>
__global__ __launch_bounds__(256)
void node_kernel(const float* __restrict__ xin,
                 const float* __restrict__ agg,
                 const float* __restrict__ epsp,
                 const float* __restrict__ w1, const float* __restrict__ b1,
                 const float* __restrict__ w2, const float* __restrict__ b2,
                 const float* __restrict__ rw, const float* __restrict__ rb,
                 float* __restrict__ y, float* __restrict__ stats,
                 const float* __restrict__ pstats,
                 const float* __restrict__ pg, const float* __restrict__ pbe) {
    __shared__ __align__(16) float s_w1[WIN * 16];
    __shared__ __align__(16) float s_w2[256];
    __shared__ __align__(16) float s_rw[WIN * 16];
    __shared__ __align__(16) float s_b[48];       // b1 | b2 | rb
    __shared__ float s_sc[16], s_sh[16];
    __shared__ float s_sum[16], s_sq[16];

    int tid = threadIdx.x;
    for (int i = tid; i < WIN * 16; i += blockDim.x) { s_w1[i] = w1[i]; s_rw[i] = rw[i]; }
    for (int i = tid; i < 256; i += blockDim.x) s_w2[i] = w2[i];
    if (tid < 16) {
        s_b[tid] = b1[tid]; s_b[16 + tid] = b2[tid]; s_b[32 + tid] = rb[tid];
        s_sum[tid] = 0.0f; s_sq[tid] = 0.0f;
        if (PREVBN) {
            const float invN = 1.0f / (float)NN;
            float mu = pstats[tid] * invN;
            float var = pstats[16 + tid] * invN - mu * mu;
            float sc = pg[tid] * rsqrtf(var + 1e-5f);
            s_sc[tid] = sc;
            s_sh[tid] = pbe[tid] - sc * mu;
        }
    }
    __syncthreads();

    float ep = 1.0f + epsp[0];
    int i = blockIdx.x * blockDim.x + tid;
    float yv[16];
    if (i < NN) {
        float xr[WIN], hp[WIN];
        const float4* xp = (const float4*)(xin + (size_t)i * WIN);
        const float4* ap = (const float4*)(agg + (size_t)i * WIN);
        float dg = PREVBN ? (float)min(__ldg(&g_cnt[i]), CAP) : 0.0f;
#pragma unroll
        for (int k = 0; k < WIN / 4; k++) {
            float4 xv = xp[k];
            float4 av = ap[k];
            float xs[4] = {xv.x, xv.y, xv.z, xv.w};
            float as[4] = {av.x, av.y, av.z, av.w};
#pragma unroll
            for (int j = 0; j < 4; j++) {
                int f = 4 * k + j;
                float xx, aa;
                if (PREVBN) {
                    float sc = s_sc[f], sh = s_sh[f];
                    xx = fmaf(sc, xs[j], sh);
                    aa = fmaf(sc, as[j], dg * sh);
                } else {
                    xx = xs[j];
                    aa = as[j];
                }
                xr[f] = xx;
                hp[f] = fmaf(ep, xx, aa);
            }
        }

        // ---- stage 1: zp = hp @ W1 + b1 (packed f32x2) ----
        ull zp[8];
        {
            const ull* bp = (const ull*)s_b;                 // b1 pairs
#pragma unroll
            for (int j = 0; j < 8; j++) zp[j] = bp[j];
            const ulonglong2* w1v = (const ulonglong2*)s_w1; // 4 per k-row
#pragma unroll
            for (int k = 0; k < WIN; k++) {
                ull h2 = pack2(hp[k], hp[k]);
#pragma unroll
                for (int m = 0; m < 4; m++) {
                    ulonglong2 w = w1v[k * 4 + m];
                    zp[2 * m + 0] = fma2(h2, w.x, zp[2 * m + 0]);
                    zp[2 * m + 1] = fma2(h2, w.y, zp[2 * m + 1]);
                }
            }
        }
        // activation (scalar)
        float z[16];
#pragma unroll
        for (int j = 0; j < 8; j++) {
            float a, b;
            unpack2(zp[j], a, b);
            z[2 * j]     = (ACT == 0) ? (a > 0.0f ? a : 0.01f * a) : fmaxf(a, 0.0f);
            z[2 * j + 1] = (ACT == 0) ? (b > 0.0f ? b : 0.01f * b) : fmaxf(b, 0.0f);
        }

        // ---- stage 2: yp = z @ W2 + (b2 + rb) + xr @ RW (packed f32x2) ----
        ull yp[8];
        {
#pragma unroll
            for (int j = 0; j < 8; j++)
                yp[j] = pack2(s_b[16 + 2 * j] + s_b[32 + 2 * j],
                              s_b[17 + 2 * j] + s_b[33 + 2 * j]);
            const ulonglong2* w2v = (const ulonglong2*)s_w2;
#pragma unroll
            for (int k = 0; k < 16; k++) {
                ull z2 = pack2(z[k], z[k]);
#pragma unroll
                for (int m = 0; m < 4; m++) {
                    ulonglong2 w = w2v[k * 4 + m];
                    yp[2 * m + 0] = fma2(z2, w.x, yp[2 * m + 0]);
                    yp[2 * m + 1] = fma2(z2, w.y, yp[2 * m + 1]);
                }
            }
            const ulonglong2* rwv = (const ulonglong2*)s_rw;
#pragma unroll
            for (int k = 0; k < WIN; k++) {
                ull x2 = pack2(xr[k], xr[k]);
#pragma unroll
                for (int m = 0; m < 4; m++) {
                    ulonglong2 w = rwv[k * 4 + m];
                    yp[2 * m + 0] = fma2(x2, w.x, yp[2 * m + 0]);
                    yp[2 * m + 1] = fma2(x2, w.y, yp[2 * m + 1]);
                }
            }
        }
#pragma unroll
        for (int j = 0; j < 8; j++) unpack2(yp[j], yv[2 * j], yv[2 * j + 1]);

        float4* ypr = (float4*)(y + (size_t)i * 16);
#pragma unroll
        for (int k = 0; k < 4; k++)
            ypr[k] = make_float4(yv[4 * k], yv[4 * k + 1], yv[4 * k + 2], yv[4 * k + 3]);
    } else {
#pragma unroll
        for (int o = 0; o < 16; o++) yv[o] = 0.0f;
    }

    // BN partial sums: warp butterfly reduce -> shared atomics -> global atomics.
#pragma unroll
    for (int o = 0; o < 16; o++) {
        float v = yv[o], q = yv[o] * yv[o];
#pragma unroll
        for (int off = 16; off; off >>= 1) {
            v += __shfl_xor_sync(0xffffffffu, v, off);
            q += __shfl_xor_sync(0xffffffffu, q, off);
        }
        if ((tid & 31) == 0) { atomicAdd(&s_sum[o], v); atomicAdd(&s_sq[o], q); }
    }
    __syncthreads();
    if (tid < 16) {
        atomicAdd(&stats[tid], s_sum[tid]);
        atomicAdd(&stats[16 + tid], s_sq[tid]);
    }
}

// ---------------------------------------------------------------------------
// BatchNorm finalize (in place) — final output only.
// ---------------------------------------------------------------------------
__global__ void bn_kernel(float* __restrict__ y, const float* __restrict__ stats,
                          const float* __restrict__ g, const float* __restrict__ be) {
    int t = blockIdx.x * blockDim.x + threadIdx.x;
    if (t >= NN * 4) return;
    int f0 = (t & 3) * 4;
    float4 v = ((float4*)y)[t];
    float vv[4] = {v.x, v.y, v.z, v.w};
    const float invN = 1.0f / (float)NN;
    float out[4];
#pragma unroll
    for (int j = 0; j < 4; j++) {
        int f = f0 + j;
        float mu = __ldg(stats + f) * invN;
        float var = __ldg(stats + 16 + f) * invN - mu * mu;
        float sc = __ldg(g + f) * rsqrtf(var + 1e-5f);
        out[j] = (vv[j] - mu) * sc + __ldg(be + f);
    }
    ((float4*)y)[t] = make_float4(out[0], out[1], out[2], out[3]);
}

// ---------------------------------------------------------------------------
// kernel_launch: zero, fill, 3 x (gather, node), final bn. 9 launches.
// ---------------------------------------------------------------------------
extern "C" void kernel_launch(void* const* d_in, const int* in_sizes, int n_in,
                              void* d_out, int out_size) {
    const float* x    = (const float*)d_in[0];
    const int*   ei   = (const int*)d_in[1];
    const int*   src  = ei;
    const int*   dst  = ei + EE;
    const float* eps1 = (const float*)d_in[2];
    const float* w11  = (const float*)d_in[3];
    const float* b11  = (const float*)d_in[4];
    const float* w12  = (const float*)d_in[5];
    const float* b12  = (const float*)d_in[6];
    const float* rw1  = (const float*)d_in[7];
    const float* rb1  = (const float*)d_in[8];
    const float* g1   = (const float*)d_in[9];
    const float* be1  = (const float*)d_in[10];
    const float* eps2 = (const float*)d_in[11];
    const float* w21  = (const float*)d_in[12];
    const float* b21  = (const float*)d_in[13];
    const float* w22  = (const float*)d_in[14];
    const float* b22  = (const float*)d_in[15];
    const float* rw2  = (const float*)d_in[16];
    const float* rb2  = (const float*)d_in[17];
    const float* g2   = (const float*)d_in[18];
    const float* be2  = (const float*)d_in[19];
    const float* eps3 = (const float*)d_in[20];
    const float* w31  = (const float*)d_in[21];
    const float* b31  = (const float*)d_in[22];
    const float* w32  = (const float*)d_in[23];
    const float* b32  = (const float*)d_in[24];
    const float* rw3  = (const float*)d_in[25];
    const float* rb3  = (const float*)d_in[26];
    const float* g3   = (const float*)d_in[27];
    const float* be3  = (const float*)d_in[28];

    float *agg, *h1, *h2, *stats;
    cudaGetSymbolAddress((void**)&agg,   g_agg);
    cudaGetSymbolAddress((void**)&h1,    g_h1);
    cudaGetSymbolAddress((void**)&h2,    g_h2);
    cudaGetSymbolAddress((void**)&stats, g_stats);
    float* out = (float*)d_out;

    const int TB = 256;
    const int ge = (EE / 4 + TB - 1) / TB;
    const int gn = (NN + TB - 1) / TB;
    const int gb = (NN * 4 + TB - 1) / TB;
    const int gg = (NN * 32 + TB - 1) / TB;   // warp per node

    // ---- bucket adjacency build ----
    zero_kernel<<<gn, TB>>>();
    fill_kernel<<<ge, TB>>>(src, dst);

    // ---- block 1: GIN(8->16->16, LeakyReLU) + residual; y1 stays RAW ----
    gather_kernel<2><<<gg, TB>>>(x, agg);
    node_kernel<8, 0, 0><<<gn, TB>>>(x, agg, eps1, w11, b11, w12, b12, rw1, rb1,
                                     h1, stats, nullptr, nullptr, nullptr);

    // ---- block 2: gather raw y1; node folds bn1 affine; y2 stays RAW ----
    gather_kernel<4><<<gg, TB>>>(h1, agg);
    node_kernel<16, 1, 1><<<gn, TB>>>(h1, agg, eps2, w21, b21, w22, b22, rw2, rb2,
                                      h2, stats + 32, stats, g1, be1);

    // ---- block 3: gather raw y2; node folds bn2 affine; final bn ----
    gather_kernel<4><<<gg, TB>>>(h2, agg);
    node_kernel<16, 1, 1><<<gn, TB>>>(h2, agg, eps3, w31, b31, w32, b32, rw3, rb3,
                                      out, stats + 64, stats + 32, g2, be2);
    bn_kernel<<<gb, TB>>>(out, stats + 64, g3, be3);
}

// round 16
// speedup vs baseline: 1.4291x; 1.0019x over previous
#include <cuda_runtime.h>
#include <math.h>

#define NN 100000
#define EE 5000000
#define CAP 128                     // bucket capacity; P(deg>=128) ~ 1e-18/node

typedef unsigned long long ull;

// Scratch (no allocations allowed).
__device__ __align__(16) float g_agg[NN * 16];
__device__ __align__(16) float g_h1[NN * 16];
__device__ __align__(16) float g_h2[NN * 16];
__device__ float g_stats[96];       // 3 layers x (16 sum | 16 sumsq)
__device__ int   g_cnt[NN];         // per-node degree counters
__device__ int   g_bucket[NN * CAP];

// ---- packed fp32x2 helpers (sm_103a FFMA2 path, PTX-only) ----
__device__ __forceinline__ ull pack2(float a, float b) {
    ull r; asm("mov.b64 %0, {%1, %2};" : "=l"(r) : "f"(a), "f"(b)); return r;
}
__device__ __forceinline__ void unpack2(ull v, float& a, float& b) {
    asm("mov.b64 {%0, %1}, %2;" : "=f"(a), "=f"(b) : "l"(v));
}
__device__ __forceinline__ ull fma2(ull a, ull b, ull c) {
    ull d; asm("fma.rn.f32x2 %0, %1, %2, %3;" : "=l"(d) : "l"(a), "l"(b), "l"(c));
    return d;
}

// ---------------------------------------------------------------------------
// zero: per-node counters + all BN stats.
// ---------------------------------------------------------------------------
__global__ void zero_kernel() {
    int i = blockIdx.x * blockDim.x + threadIdx.x;
    if (i < NN) g_cnt[i] = 0;
    if (i < 96) g_stats[i] = 0.0f;
}

// ---------------------------------------------------------------------------
// Bucket fill: bucket[dst*CAP + cnt[dst]++] = src. 4 edges/thread.
// ---------------------------------------------------------------------------
__global__ void fill_kernel(const int* __restrict__ src, const int* __restrict__ dst) {
    int t = blockIdx.x * blockDim.x + threadIdx.x;
    if (t >= EE / 4) return;
    int4 s4 = ((const int4*)src)[t];
    int4 d4 = ((const int4*)dst)[t];
    int ss[4] = {s4.x, s4.y, s4.z, s4.w};
    int dd[4] = {d4.x, d4.y, d4.z, d4.w};
#pragma unroll
    for (int j = 0; j < 4; j++) {
        int pos = atomicAdd(&g_cnt[dd[j]], 1);
        if (pos < CAP) g_bucket[dd[j] * CAP + pos] = ss[j];
    }
}

// ---------------------------------------------------------------------------
// Bucket gather (fp32): one warp per node. Lane (g, c): group g strides
// edges, chunk c reads float4 #c of the neighbor row (coalesced 64B).
// Unroll x4, dual accumulators. W4 = float4s per row (2 -> 8 feat, 4 -> 16).
// Reads RAW (pre-BN) features; the node kernel folds the BN affine in.
// ---------------------------------------------------------------------------
template <int W4>
__global__ void gather_kernel(const float* __restrict__ x, float* __restrict__ agg) {
    const int NG = 32 / W4;
    int gw = (blockIdx.x * blockDim.x + threadIdx.x) >> 5;
    if (gw >= NN) return;
    int lane = threadIdx.x & 31;
    int c = lane & (W4 - 1);
    int g = lane / W4;
    int n = min(__ldg(&g_cnt[gw]), CAP);
    const int* bk = g_bucket + (size_t)gw * CAP;
    float4 a0 = make_float4(0.f, 0.f, 0.f, 0.f);
    float4 a1 = make_float4(0.f, 0.f, 0.f, 0.f);
    const float4* xf = (const float4*)x;
    int e = g;
    for (; e + 3 * NG < n; e += 4 * NG) {
        int s0 = __ldg(bk + e);
        int s1 = __ldg(bk + e + NG);
        int s2 = __ldg(bk + e + 2 * NG);
        int s3 = __ldg(bk + e + 3 * NG);
        float4 v0 = __ldg(xf + (size_t)s0 * W4 + c);
        float4 v1 = __ldg(xf + (size_t)s1 * W4 + c);
        float4 v2 = __ldg(xf + (size_t)s2 * W4 + c);
        float4 v3 = __ldg(xf + (size_t)s3 * W4 + c);
        a0.x += v0.x; a0.y += v0.y; a0.z += v0.z; a0.w += v0.w;
        a1.x += v1.x; a1.y += v1.y; a1.z += v1.z; a1.w += v1.w;
        a0.x += v2.x; a0.y += v2.y; a0.z += v2.z; a0.w += v2.w;
        a1.x += v3.x; a1.y += v3.y; a1.z += v3.z; a1.w += v3.w;
    }
    for (; e < n; e += NG) {
        int s = __ldg(bk + e);
        float4 v = __ldg(xf + (size_t)s * W4 + c);
        a0.x += v.x; a0.y += v.y; a0.z += v.z; a0.w += v.w;
    }
    float4 acc = make_float4(a0.x + a1.x, a0.y + a1.y, a0.z + a1.z, a0.w + a1.w);
#pragma unroll
    for (int off = W4; off < 32; off <<= 1) {
        acc.x += __shfl_xor_sync(0xffffffffu, acc.x, off);
        acc.y += __shfl_xor_sync(0xffffffffu, acc.y, off);
        acc.z += __shfl_xor_sync(0xffffffffu, acc.z, off);
        acc.w += __shfl_xor_sync(0xffffffffu, acc.w, off);
    }
    if (lane < W4) ((float4*)agg)[(size_t)gw * W4 + lane] = acc;
}

// ---------------------------------------------------------------------------
// Fused node update, 2 threads per node (half h = tid&1 owns output features
// h*8..h*8+7). Doubles warp count (latency hiding) and halves per-thread
// FMA2/LDS work. Partner halves exchange z via 8 shfl_xor(1). All threads
// stay converged (clamped index; store/stats guarded) so full-mask shuffles
// are safe. If PREVBN: fold previous layer's BN affine (x = sc*xin+sh,
// agg_bn = sc*agg + deg*sh). ACT: 0 = LeakyReLU(0.01), 1 = ReLU.
// ---------------------------------------------------------------------------
template <int WIN, int ACT, int PREVBN>
__global__ __launch_bounds__(256)
void node_kernel(const float* __restrict__ xin,
                 const float* __restrict__ agg,
                 const float* __restrict__ epsp,
                 const float* __restrict__ w1, const float* __restrict__ b1,
                 const float* __restrict__ w2, const float* __restrict__ b2,
                 const float* __restrict__ rw, const float* __restrict__ rb,
                 float* __restrict__ y, float* __restrict__ stats,
                 const float* __restrict__ pstats,
                 const float* __restrict__ pg, const float* __restrict__ pbe) {
    __shared__ __align__(16) float s_w1[WIN * 16];
    __shared__ __align__(16) float s_w2[256];
    __shared__ __align__(16) float s_rw[WIN * 16];
    __shared__ __align__(16) float s_b[48];       // b1 | b2 | rb
    __shared__ float s_sc[16], s_sh[16];
    __shared__ float s_sum[16], s_sq[16];

    int tid = threadIdx.x;
    for (int i = tid; i < WIN * 16; i += blockDim.x) { s_w1[i] = w1[i]; s_rw[i] = rw[i]; }
    for (int i = tid; i < 256; i += blockDim.x) s_w2[i] = w2[i];
    if (tid < 16) {
        s_b[tid] = b1[tid]; s_b[16 + tid] = b2[tid]; s_b[32 + tid] = rb[tid];
        s_sum[tid] = 0.0f; s_sq[tid] = 0.0f;
        if (PREVBN) {
            const float invN = 1.0f / (float)NN;
            float mu = pstats[tid] * invN;
            float var = pstats[16 + tid] * invN - mu * mu;
            float sc = pg[tid] * rsqrtf(var + 1e-5f);
            s_sc[tid] = sc;
            s_sh[tid] = pbe[tid] - sc * mu;
        }
    }
    __syncthreads();

    float ep = 1.0f + epsp[0];
    int h = tid & 1;                               // output half
    int i = blockIdx.x * (blockDim.x >> 1) + (tid >> 1);
    bool live = (i < NN);
    int ic = live ? i : (NN - 1);                  // clamped: keep warp converged

    float xr[WIN], hp[WIN];
    {
        const float4* xp = (const float4*)(xin + (size_t)ic * WIN);
        const float4* ap = (const float4*)(agg + (size_t)ic * WIN);
        float dg = PREVBN ? (float)min(__ldg(&g_cnt[ic]), CAP) : 0.0f;
#pragma unroll
        for (int k = 0; k < WIN / 4; k++) {
            float4 xv = __ldg(xp + k);
            float4 av = __ldg(ap + k);
            float xs[4] = {xv.x, xv.y, xv.z, xv.w};
            float as[4] = {av.x, av.y, av.z, av.w};
#pragma unroll
            for (int j = 0; j < 4; j++) {
                int f = 4 * k + j;
                float xx, aa;
                if (PREVBN) {
                    float sc = s_sc[f], sh = s_sh[f];
                    xx = fmaf(sc, xs[j], sh);
                    aa = fmaf(sc, as[j], dg * sh);
                } else {
                    xx = xs[j];
                    aa = as[j];
                }
                xr[f] = xx;
                hp[f] = fmaf(ep, xx, aa);
            }
        }
    }

    // ---- stage 1: my 8 outputs of z = act(hp @ W1 + b1) (packed f32x2) ----
    float z[8];
    {
        ull zp[4];
        const ull* bp = (const ull*)s_b;            // b1 as 8 pairs
#pragma unroll
        for (int j = 0; j < 4; j++) zp[j] = bp[h * 4 + j];
        const ulonglong2* w1v = (const ulonglong2*)s_w1;  // 4 per 16-wide row
#pragma unroll
        for (int k = 0; k < WIN; k++) {
            ull h2 = pack2(hp[k], hp[k]);
            ulonglong2 wa = w1v[k * 4 + 2 * h];
            ulonglong2 wb = w1v[k * 4 + 2 * h + 1];
            zp[0] = fma2(h2, wa.x, zp[0]);
            zp[1] = fma2(h2, wa.y, zp[1]);
            zp[2] = fma2(h2, wb.x, zp[2]);
            zp[3] = fma2(h2, wb.y, zp[3]);
        }
#pragma unroll
        for (int j = 0; j < 4; j++) {
            float a, b;
            unpack2(zp[j], a, b);
            z[2 * j]     = (ACT == 0) ? (a > 0.0f ? a : 0.01f * a) : fmaxf(a, 0.0f);
            z[2 * j + 1] = (ACT == 0) ? (b > 0.0f ? b : 0.01f * b) : fmaxf(b, 0.0f);
        }
    }

    // ---- exchange partner's z half; build full z[16] ----
    float zf[16];
    {
        float zo[8];
#pragma unroll
        for (int j = 0; j < 8; j++) zo[j] = __shfl_xor_sync(0xffffffffu, z[j], 1);
#pragma unroll
        for (int j = 0; j < 8; j++) {
            zf[j]     = h ? zo[j] : z[j];     // features 0..7
            zf[8 + j] = h ? z[j]  : zo[j];    // features 8..15
        }
    }

    // ---- stage 2: my 8 outputs of y = zf@W2 + b2 + rb + xr@RW ----
    float yv[8];
    {
        ull yp[4];
#pragma unroll
        for (int j = 0; j < 4; j++)
            yp[j] = pack2(s_b[16 + h * 8 + 2 * j] + s_b[32 + h * 8 + 2 * j],
                          s_b[17 + h * 8 + 2 * j] + s_b[33 + h * 8 + 2 * j]);
        const ulonglong2* w2v = (const ulonglong2*)s_w2;
#pragma unroll
        for (int k = 0; k < 16; k++) {
            ull z2 = pack2(zf[k], zf[k]);
            ulonglong2 wa = w2v[k * 4 + 2 * h];
            ulonglong2 wb = w2v[k * 4 + 2 * h + 1];
            yp[0] = fma2(z2, wa.x, yp[0]);
            yp[1] = fma2(z2, wa.y, yp[1]);
            yp[2] = fma2(z2, wb.x, yp[2]);
            yp[3] = fma2(z2, wb.y, yp[3]);
        }
        const ulonglong2* rwv = (const ulonglong2*)s_rw;
#pragma unroll
        for (int k = 0; k < WIN; k++) {
            ull x2 = pack2(xr[k], xr[k]);
            ulonglong2 wa = rwv[k * 4 + 2 * h];
            ulonglong2 wb = rwv[k * 4 + 2 * h + 1];
            yp[0] = fma2(x2, wa.x, yp[0]);
            yp[1] = fma2(x2, wa.y, yp[1]);
            yp[2] = fma2(x2, wb.x, yp[2]);
            yp[3] = fma2(x2, wb.y, yp[3]);
        }
#pragma unroll
        for (int j = 0; j < 4; j++) unpack2(yp[j], yv[2 * j], yv[2 * j + 1]);
    }

    if (live) {
        float4* ypr = (float4*)(y + (size_t)i * 16 + h * 8);
        ypr[0] = make_float4(yv[0], yv[1], yv[2], yv[3]);
        ypr[1] = make_float4(yv[4], yv[5], yv[6], yv[7]);
    } else {
#pragma unroll
        for (int j = 0; j < 8; j++) yv[j] = 0.0f;
    }

    // ---- BN stats: parity-preserving butterfly (offsets 2,4,8,16), then
    // lanes 0 (features 0-7) and 1 (features 8-15) hit shared atomics. ----
    {
        float qs[8];
#pragma unroll
        for (int j = 0; j < 8; j++) qs[j] = yv[j] * yv[j];
#pragma unroll
        for (int off = 2; off < 32; off <<= 1) {
#pragma unroll
            for (int j = 0; j < 8; j++) {
                yv[j] += __shfl_xor_sync(0xffffffffu, yv[j], off);
                qs[j] += __shfl_xor_sync(0xffffffffu, qs[j], off);
            }
        }
        int lane = tid & 31;
        if (lane < 2) {
#pragma unroll
            for (int j = 0; j < 8; j++) {
                atomicAdd(&s_sum[lane * 8 + j], yv[j]);
                atomicAdd(&s_sq[lane * 8 + j], qs[j]);
            }
        }
    }
    __syncthreads();
    if (tid < 16) {
        atomicAdd(&stats[tid], s_sum[tid]);
        atomicAdd(&stats[16 + tid], s_sq[tid]);
    }
}

// ---------------------------------------------------------------------------
// BatchNorm finalize (in place) — final output only.
// ---------------------------------------------------------------------------
__global__ void bn_kernel(float* __restrict__ y, const float* __restrict__ stats,
                          const float* __restrict__ g, const float* __restrict__ be) {
    int t = blockIdx.x * blockDim.x + threadIdx.x;
    if (t >= NN * 4) return;
    int f0 = (t & 3) * 4;
    float4 v = ((float4*)y)[t];
    float vv[4] = {v.x, v.y, v.z, v.w};
    const float invN = 1.0f / (float)NN;
    float out[4];
#pragma unroll
    for (int j = 0; j < 4; j++) {
        int f = f0 + j;
        float mu = __ldg(stats + f) * invN;
        float var = __ldg(stats + 16 + f) * invN - mu * mu;
        float sc = __ldg(g + f) * rsqrtf(var + 1e-5f);
        out[j] = (vv[j] - mu) * sc + __ldg(be + f);
    }
    ((float4*)y)[t] = make_float4(out[0], out[1], out[2], out[3]);
}

// ---------------------------------------------------------------------------
// kernel_launch: zero, fill, 3 x (gather, node), final bn. 9 launches.
// ---------------------------------------------------------------------------
extern "C" void kernel_launch(void* const* d_in, const int* in_sizes, int n_in,
                              void* d_out, int out_size) {
    const float* x    = (const float*)d_in[0];
    const int*   ei   = (const int*)d_in[1];
    const int*   src  = ei;
    const int*   dst  = ei + EE;
    const float* eps1 = (const float*)d_in[2];
    const float* w11  = (const float*)d_in[3];
    const float* b11  = (const float*)d_in[4];
    const float* w12  = (const float*)d_in[5];
    const float* b12  = (const float*)d_in[6];
    const float* rw1  = (const float*)d_in[7];
    const float* rb1  = (const float*)d_in[8];
    const float* g1   = (const float*)d_in[9];
    const float* be1  = (const float*)d_in[10];
    const float* eps2 = (const float*)d_in[11];
    const float* w21  = (const float*)d_in[12];
    const float* b21  = (const float*)d_in[13];
    const float* w22  = (const float*)d_in[14];
    const float* b22  = (const float*)d_in[15];
    const float* rw2  = (const float*)d_in[16];
    const float* rb2  = (const float*)d_in[17];
    const float* g2   = (const float*)d_in[18];
    const float* be2  = (const float*)d_in[19];
    const float* eps3 = (const float*)d_in[20];
    const float* w31  = (const float*)d_in[21];
    const float* b31  = (const float*)d_in[22];
    const float* w32  = (const float*)d_in[23];
    const float* b32  = (const float*)d_in[24];
    const float* rw3  = (const float*)d_in[25];
    const float* rb3  = (const float*)d_in[26];
    const float* g3   = (const float*)d_in[27];
    const float* be3  = (const float*)d_in[28];

    float *agg, *h1, *h2, *stats;
    cudaGetSymbolAddress((void**)&agg,   g_agg);
    cudaGetSymbolAddress((void**)&h1,    g_h1);
    cudaGetSymbolAddress((void**)&h2,    g_h2);
    cudaGetSymbolAddress((void**)&stats, g_stats);
    float* out = (float*)d_out;

    const int TB = 256;
    const int ge  = (EE / 4 + TB - 1) / TB;
    const int gn  = (NN + TB - 1) / TB;
    const int gp  = (NN * 2 + TB - 1) / TB;   // 2 threads per node
    const int gb  = (NN * 4 + TB - 1) / TB;
    const int gg  = (NN * 32 + TB - 1) / TB;  // warp per node

    // ---- bucket adjacency build ----
    zero_kernel<<<gn, TB>>>();
    fill_kernel<<<ge, TB>>>(src, dst);

    // ---- block 1: GIN(8->16->16, LeakyReLU) + residual; y1 stays RAW ----
    gather_kernel<2><<<gg, TB>>>(x, agg);
    node_kernel<8, 0, 0><<<gp, TB>>>(x, agg, eps1, w11, b11, w12, b12, rw1, rb1,
                                     h1, stats, nullptr, nullptr, nullptr);

    // ---- block 2: gather raw y1; node folds bn1 affine; y2 stays RAW ----
    gather_kernel<4><<<gg, TB>>>(h1, agg);
    node_kernel<16, 1, 1><<<gp, TB>>>(h1, agg, eps2, w21, b21, w22, b22, rw2, rb2,
                                      h2, stats + 32, stats, g1, be1);

    // ---- block 3: gather raw y2; node folds bn2 affine; final bn ----
    gather_kernel<4><<<gg, TB>>>(h2, agg);
    node_kernel<16, 1, 1><<<gp, TB>>>(h2, agg, eps3, w31, b31, w32, b32, rw3, rb3,
                                      out, stats + 64, stats + 32, g2, be2);
    bn_kernel<<<gb, TB>>>(out, stats + 64, g3, be3);
}

// round 17
// speedup vs baseline: 1.4891x; 1.0419x over previous
#include <cuda_runtime.h>
#include <math.h>

#define NN 100000
#define EE 5000000
#define CAP 128                     // bucket capacity; P(deg>=128) ~ 1e-18/node

typedef unsigned long long ull;

// Scratch (no allocations allowed).
__device__ __align__(16) float g_agg[NN * 16];
__device__ __align__(16) float g_h1[NN * 16];
__device__ __align__(16) float g_h2[NN * 16];
__device__ float g_stats[96];       // 3 layers x (16 sum | 16 sumsq)
__device__ int   g_cnt[NN];         // degree counters; cleared by bn tail of the
                                    // previous invocation (zero-init at load)
__device__ int   g_bucket[NN * CAP];

// ---- packed fp32x2 helpers (sm_103a FFMA2 path, PTX-only) ----
__device__ __forceinline__ ull pack2(float a, float b) {
    ull r; asm("mov.b64 %0, {%1, %2};" : "=l"(r) : "f"(a), "f"(b)); return r;
}
__device__ __forceinline__ void unpack2(ull v, float& a, float& b) {
    asm("mov.b64 {%0, %1}, %2;" : "=f"(a), "=f"(b) : "l"(v));
}
__device__ __forceinline__ ull fma2(ull a, ull b, ull c) {
    ull d; asm("fma.rn.f32x2 %0, %1, %2, %3;" : "=l"(d) : "l"(a), "l"(b), "l"(c));
    return d;
}

// ---------------------------------------------------------------------------
// Bucket fill (first kernel): clears BN stats, then
// bucket[dst*CAP + cnt[dst]++] = src. 4 edges/thread. cnt was zeroed by the
// previous invocation's bn_kernel (or module zero-init on the first call).
// ---------------------------------------------------------------------------
__global__ void fill_kernel(const int* __restrict__ src, const int* __restrict__ dst) {
    int t = blockIdx.x * blockDim.x + threadIdx.x;
    if (t < 96) g_stats[t] = 0.0f;
    if (t >= EE / 4) return;
    int4 s4 = ((const int4*)src)[t];
    int4 d4 = ((const int4*)dst)[t];
    int ss[4] = {s4.x, s4.y, s4.z, s4.w};
    int dd[4] = {d4.x, d4.y, d4.z, d4.w};
#pragma unroll
    for (int j = 0; j < 4; j++) {
        int pos = atomicAdd(&g_cnt[dd[j]], 1);
        if (pos < CAP) g_bucket[dd[j] * CAP + pos] = ss[j];
    }
}

// ---------------------------------------------------------------------------
// Bucket gather (fp32). NPW nodes per warp (2 for 16-wide rows, 4 for 8-wide).
// Each node owned by LPN = 32/NPW lanes: GPN = LPN/W4 groups of W4 chunk-lanes.
// A group processes 4 CONTIGUOUS edges per iteration: one int4 index load
// (coalesced, 16B-aligned since CAP%4==0) + 4 row loads. deg~50 => ~3 full
// iterations per group, scalar tail <=3 edges on one group only.
// Requires NN % NPW == 0 (100000 % 2 == 100000 % 4 == 0) so every warp is
// full and full-mask shuffles are safe.
// ---------------------------------------------------------------------------
template <int W4, int NPW>
__global__ void gather_kernel(const float* __restrict__ x, float* __restrict__ agg) {
    const int LPN = 32 / NPW;        // lanes per node
    const int GPN = LPN / W4;        // groups per node (= 4 for both configs)
    int warp = (blockIdx.x * blockDim.x + threadIdx.x) >> 5;
    int lane = threadIdx.x & 31;
    int sub = lane / LPN;            // node slot within warp
    int l = lane & (LPN - 1);
    int c = l & (W4 - 1);            // chunk (float4) within row
    int g = l / W4;                  // edge group
    int node = warp * NPW + sub;     // exact grid: node < NN always
    int n = min(__ldg(&g_cnt[node]), CAP);
    const int* bk = g_bucket + (size_t)node * CAP;
    const float4* xf = (const float4*)x;

    float4 a0 = make_float4(0.f, 0.f, 0.f, 0.f);
    float4 a1 = make_float4(0.f, 0.f, 0.f, 0.f);
    for (int base = 4 * g; base + 4 <= n; base += 4 * GPN) {
        int4 s = *(const int4*)(bk + base);
        float4 v0 = __ldg(xf + (size_t)s.x * W4 + c);
        float4 v1 = __ldg(xf + (size_t)s.y * W4 + c);
        float4 v2 = __ldg(xf + (size_t)s.z * W4 + c);
        float4 v3 = __ldg(xf + (size_t)s.w * W4 + c);
        a0.x += v0.x; a0.y += v0.y; a0.z += v0.z; a0.w += v0.w;
        a1.x += v1.x; a1.y += v1.y; a1.z += v1.z; a1.w += v1.w;
        a0.x += v2.x; a0.y += v2.y; a0.z += v2.z; a0.w += v2.w;
        a1.x += v3.x; a1.y += v3.y; a1.z += v3.z; a1.w += v3.w;
    }
    // partial last quad (n%4 edges) handled by the group owning that quad
    if (g == ((n >> 2) & (GPN - 1))) {
        for (int e = (n & ~3); e < n; e++) {
            int s = __ldg(bk + e);
            float4 v = __ldg(xf + (size_t)s * W4 + c);
            a0.x += v.x; a0.y += v.y; a0.z += v.z; a0.w += v.w;
        }
    }
    float4 acc = make_float4(a0.x + a1.x, a0.y + a1.y, a0.z + a1.z, a0.w + a1.w);
#pragma unroll
    for (int off = W4; off < LPN; off <<= 1) {
        acc.x += __shfl_xor_sync(0xffffffffu, acc.x, off);
        acc.y += __shfl_xor_sync(0xffffffffu, acc.y, off);
        acc.z += __shfl_xor_sync(0xffffffffu, acc.z, off);
        acc.w += __shfl_xor_sync(0xffffffffu, acc.w, off);
    }
    if (l < W4) ((float4*)agg)[(size_t)node * W4 + c] = acc;
}

// ---------------------------------------------------------------------------
// Fused node update, 2 threads per node (half h = tid&1 owns output features
// h*8..h*8+7). Partner halves exchange z via 8 shfl_xor(1). All threads stay
// converged (clamped index; store/stats guarded). If PREVBN: fold previous
// layer's BN affine (x = sc*xin+sh, agg_bn = sc*agg + deg*sh).
// ACT: 0 = LeakyReLU(0.01), 1 = ReLU.  (unchanged from R16 — proven)
// ---------------------------------------------------------------------------
template <int WIN, int ACT, int PREVBN>
__global__ __launch_bounds__(256)
void node_kernel(const float* __restrict__ xin,
                 const float* __restrict__ agg,
                 const float* __restrict__ epsp,
                 const float* __restrict__ w1, const float* __restrict__ b1,
                 const float* __restrict__ w2, const float* __restrict__ b2,
                 const float* __restrict__ rw, const float* __restrict__ rb,
                 float* __restrict__ y, float* __restrict__ stats,
                 const float* __restrict__ pstats,
                 const float* __restrict__ pg, const float* __restrict__ pbe) {
    __shared__ __align__(16) float s_w1[WIN * 16];
    __shared__ __align__(16) float s_w2[256];
    __shared__ __align__(16) float s_rw[WIN * 16];
    __shared__ __align__(16) float s_b[48];       // b1 | b2 | rb
    __shared__ float s_sc[16], s_sh[16];
    __shared__ float s_sum[16], s_sq[16];

    int tid = threadIdx.x;
    for (int i = tid; i < WIN * 16; i += blockDim.x) { s_w1[i] = w1[i]; s_rw[i] = rw[i]; }
    for (int i = tid; i < 256; i += blockDim.x) s_w2[i] = w2[i];
    if (tid < 16) {
        s_b[tid] = b1[tid]; s_b[16 + tid] = b2[tid]; s_b[32 + tid] = rb[tid];
        s_sum[tid] = 0.0f; s_sq[tid] = 0.0f;
        if (PREVBN) {
            const float invN = 1.0f / (float)NN;
            float mu = pstats[tid] * invN;
            float var = pstats[16 + tid] * invN - mu * mu;
            float sc = pg[tid] * rsqrtf(var + 1e-5f);
            s_sc[tid] = sc;
            s_sh[tid] = pbe[tid] - sc * mu;
        }
    }
    __syncthreads();

    float ep = 1.0f + epsp[0];
    int h = tid & 1;                               // output half
    int i = blockIdx.x * (blockDim.x >> 1) + (tid >> 1);
    bool live = (i < NN);
    int ic = live ? i : (NN - 1);                  // clamped: keep warp converged

    float xr[WIN], hp[WIN];
    {
        const float4* xp = (const float4*)(xin + (size_t)ic * WIN);
        const float4* ap = (const float4*)(agg + (size_t)ic * WIN);
        float dg = PREVBN ? (float)min(__ldg(&g_cnt[ic]), CAP) : 0.0f;
#pragma unroll
        for (int k = 0; k < WIN / 4; k++) {
            float4 xv = __ldg(xp + k);
            float4 av = __ldg(ap + k);
            float xs[4] = {xv.x, xv.y, xv.z, xv.w};
            float as[4] = {av.x, av.y, av.z, av.w};
#pragma unroll
            for (int j = 0; j < 4; j++) {
                int f = 4 * k + j;
                float xx, aa;
                if (PREVBN) {
                    float sc = s_sc[f], sh = s_sh[f];
                    xx = fmaf(sc, xs[j], sh);
                    aa = fmaf(sc, as[j], dg * sh);
                } else {
                    xx = xs[j];
                    aa = as[j];
                }
                xr[f] = xx;
                hp[f] = fmaf(ep, xx, aa);
            }
        }
    }

    // ---- stage 1: my 8 outputs of z = act(hp @ W1 + b1) (packed f32x2) ----
    float z[8];
    {
        ull zp[4];
        const ull* bp = (const ull*)s_b;            // b1 as 8 pairs
#pragma unroll
        for (int j = 0; j < 4; j++) zp[j] = bp[h * 4 + j];
        const ulonglong2* w1v = (const ulonglong2*)s_w1;  // 4 per 16-wide row
#pragma unroll
        for (int k = 0; k < WIN; k++) {
            ull h2 = pack2(hp[k], hp[k]);
            ulonglong2 wa = w1v[k * 4 + 2 * h];
            ulonglong2 wb = w1v[k * 4 + 2 * h + 1];
            zp[0] = fma2(h2, wa.x, zp[0]);
            zp[1] = fma2(h2, wa.y, zp[1]);
            zp[2] = fma2(h2, wb.x, zp[2]);
            zp[3] = fma2(h2, wb.y, zp[3]);
        }
#pragma unroll
        for (int j = 0; j < 4; j++) {
            float a, b;
            unpack2(zp[j], a, b);
            z[2 * j]     = (ACT == 0) ? (a > 0.0f ? a : 0.01f * a) : fmaxf(a, 0.0f);
            z[2 * j + 1] = (ACT == 0) ? (b > 0.0f ? b : 0.01f * b) : fmaxf(b, 0.0f);
        }
    }

    // ---- exchange partner's z half; build full z[16] ----
    float zf[16];
    {
        float zo[8];
#pragma unroll
        for (int j = 0; j < 8; j++) zo[j] = __shfl_xor_sync(0xffffffffu, z[j], 1);
#pragma unroll
        for (int j = 0; j < 8; j++) {
            zf[j]     = h ? zo[j] : z[j];     // features 0..7
            zf[8 + j] = h ? z[j]  : zo[j];    // features 8..15
        }
    }

    // ---- stage 2: my 8 outputs of y = zf@W2 + b2 + rb + xr@RW ----
    float yv[8];
    {
        ull yp[4];
#pragma unroll
        for (int j = 0; j < 4; j++)
            yp[j] = pack2(s_b[16 + h * 8 + 2 * j] + s_b[32 + h * 8 + 2 * j],
                          s_b[17 + h * 8 + 2 * j] + s_b[33 + h * 8 + 2 * j]);
        const ulonglong2* w2v = (const ulonglong2*)s_w2;
#pragma unroll
        for (int k = 0; k < 16; k++) {
            ull z2 = pack2(zf[k], zf[k]);
            ulonglong2 wa = w2v[k * 4 + 2 * h];
            ulonglong2 wb = w2v[k * 4 + 2 * h + 1];
            yp[0] = fma2(z2, wa.x, yp[0]);
            yp[1] = fma2(z2, wa.y, yp[1]);
            yp[2] = fma2(z2, wb.x, yp[2]);
            yp[3] = fma2(z2, wb.y, yp[3]);
        }
        const ulonglong2* rwv = (const ulonglong2*)s_rw;
#pragma unroll
        for (int k = 0; k < WIN; k++) {
            ull x2 = pack2(xr[k], xr[k]);
            ulonglong2 wa = rwv[k * 4 + 2 * h];
            ulonglong2 wb = rwv[k * 4 + 2 * h + 1];
            yp[0] = fma2(x2, wa.x, yp[0]);
            yp[1] = fma2(x2, wa.y, yp[1]);
            yp[2] = fma2(x2, wb.x, yp[2]);
            yp[3] = fma2(x2, wb.y, yp[3]);
        }
#pragma unroll
        for (int j = 0; j < 4; j++) unpack2(yp[j], yv[2 * j], yv[2 * j + 1]);
    }

    if (live) {
        float4* ypr = (float4*)(y + (size_t)i * 16 + h * 8);
        ypr[0] = make_float4(yv[0], yv[1], yv[2], yv[3]);
        ypr[1] = make_float4(yv[4], yv[5], yv[6], yv[7]);
    } else {
#pragma unroll
        for (int j = 0; j < 8; j++) yv[j] = 0.0f;
    }

    // ---- BN stats: parity-preserving butterfly (offsets 2,4,8,16), then
    // lanes 0 (features 0-7) and 1 (features 8-15) hit shared atomics. ----
    {
        float qs[8];
#pragma unroll
        for (int j = 0; j < 8; j++) qs[j] = yv[j] * yv[j];
#pragma unroll
        for (int off = 2; off < 32; off <<= 1) {
#pragma unroll
            for (int j = 0; j < 8; j++) {
                yv[j] += __shfl_xor_sync(0xffffffffu, yv[j], off);
                qs[j] += __shfl_xor_sync(0xffffffffu, qs[j], off);
            }
        }
        int lane = tid & 31;
        if (lane < 2) {
#pragma unroll
            for (int j = 0; j < 8; j++) {
                atomicAdd(&s_sum[lane * 8 + j], yv[j]);
                atomicAdd(&s_sq[lane * 8 + j], qs[j]);
            }
        }
    }
    __syncthreads();
    if (tid < 16) {
        atomicAdd(&stats[tid], s_sum[tid]);
        atomicAdd(&stats[16 + tid], s_sq[tid]);
    }
}

// ---------------------------------------------------------------------------
// BatchNorm finalize (in place) — final output only. Tail also clears the
// per-node degree counters for the NEXT invocation's fill (bn does not read
// g_cnt itself; node3 already consumed it — stream order makes this safe).
// ---------------------------------------------------------------------------
__global__ void bn_kernel(float* __restrict__ y, const float* __restrict__ stats,
                          const float* __restrict__ g, const float* __restrict__ be) {
    int t = blockIdx.x * blockDim.x + threadIdx.x;
    if (t < NN) g_cnt[t] = 0;
    if (t >= NN * 4) return;
    int f0 = (t & 3) * 4;
    float4 v = ((float4*)y)[t];
    float vv[4] = {v.x, v.y, v.z, v.w};
    const float invN = 1.0f / (float)NN;
    float out[4];
#pragma unroll
    for (int j = 0; j < 4; j++) {
        int f = f0 + j;
        float mu = __ldg(stats + f) * invN;
        float var = __ldg(stats + 16 + f) * invN - mu * mu;
        float sc = __ldg(g + f) * rsqrtf(var + 1e-5f);
        out[j] = (vv[j] - mu) * sc + __ldg(be + f);
    }
    ((float4*)y)[t] = make_float4(out[0], out[1], out[2], out[3]);
}

// ---------------------------------------------------------------------------
// kernel_launch: fill, 3 x (gather, node), final bn. 8 launches.
// ---------------------------------------------------------------------------
extern "C" void kernel_launch(void* const* d_in, const int* in_sizes, int n_in,
                              void* d_out, int out_size) {
    const float* x    = (const float*)d_in[0];
    const int*   ei   = (const int*)d_in[1];
    const int*   src  = ei;
    const int*   dst  = ei + EE;
    const float* eps1 = (const float*)d_in[2];
    const float* w11  = (const float*)d_in[3];
    const float* b11  = (const float*)d_in[4];
    const float* w12  = (const float*)d_in[5];
    const float* b12  = (const float*)d_in[6];
    const float* rw1  = (const float*)d_in[7];
    const float* rb1  = (const float*)d_in[8];
    const float* g1   = (const float*)d_in[9];
    const float* be1  = (const float*)d_in[10];
    const float* eps2 = (const float*)d_in[11];
    const float* w21  = (const float*)d_in[12];
    const float* b21  = (const float*)d_in[13];
    const float* w22  = (const float*)d_in[14];
    const float* b22  = (const float*)d_in[15];
    const float* rw2  = (const float*)d_in[16];
    const float* rb2  = (const float*)d_in[17];
    const float* g2   = (const float*)d_in[18];
    const float* be2  = (const float*)d_in[19];
    const float* eps3 = (const float*)d_in[20];
    const float* w31  = (const float*)d_in[21];
    const float* b31  = (const float*)d_in[22];
    const float* w32  = (const float*)d_in[23];
    const float* b32  = (const float*)d_in[24];
    const float* rw3  = (const float*)d_in[25];
    const float* rb3  = (const float*)d_in[26];
    const float* g3   = (const float*)d_in[27];
    const float* be3  = (const float*)d_in[28];

    float *agg, *h1, *h2, *stats;
    cudaGetSymbolAddress((void**)&agg,   g_agg);
    cudaGetSymbolAddress((void**)&h1,    g_h1);
    cudaGetSymbolAddress((void**)&h2,    g_h2);
    cudaGetSymbolAddress((void**)&stats, g_stats);
    float* out = (float*)d_out;

    const int TB = 256;
    const int ge  = (EE / 4 + TB - 1) / TB;
    const int gp  = (NN * 2 + TB - 1) / TB;        // 2 threads per node
    const int gb  = (NN * 4 + TB - 1) / TB;
    const int gg2 = (NN / 4) * 32 / TB;            // quarter-warp per node (8-wide)
    const int gg4 = (NN / 2) * 32 / TB;            // half-warp per node (16-wide)

    // ---- bucket adjacency build (fill also clears BN stats) ----
    fill_kernel<<<ge, TB>>>(src, dst);

    // ---- block 1: GIN(8->16->16, LeakyReLU) + residual; y1 stays RAW ----
    gather_kernel<2, 4><<<gg2, TB>>>(x, agg);
    node_kernel<8, 0, 0><<<gp, TB>>>(x, agg, eps1, w11, b11, w12, b12, rw1, rb1,
                                     h1, stats, nullptr, nullptr, nullptr);

    // ---- block 2: gather raw y1; node folds bn1 affine; y2 stays RAW ----
    gather_kernel<4, 2><<<gg4, TB>>>(h1, agg);
    node_kernel<16, 1, 1><<<gp, TB>>>(h1, agg, eps2, w21, b21, w22, b22, rw2, rb2,
                                      h2, stats + 32, stats, g1, be1);

    // ---- block 3: gather raw y2; node folds bn2 affine; final bn ----
    gather_kernel<4, 2><<<gg4, TB>>>(h2, agg);
    node_kernel<16, 1, 1><<<gp, TB>>>(h2, agg, eps3, w31, b31, w32, b32, rw3, rb3,
                                      out, stats + 64, stats + 32, g2, be2);
    bn_kernel<<<gb, TB>>>(out, stats + 64, g3, be3);
}